// round 16
// baseline (speedup 1.0000x reference)
#include <cuda_runtime.h>
#include <cuda_bf16.h>
#include <math.h>
#include <cstdint>

#define B_ 32
#define P_ 2048
#define D_ 1024
#define TD_ 768
#define PR_ 512
#define EPS_ 1e-5f

__device__ __align__(256) __nv_bfloat16 g_xh[(size_t)B_*P_*D_];
__device__ __align__(256) __nv_bfloat16 g_gh[(size_t)B_*P_*D_];
__device__ __align__(256) __nv_bfloat16 g_wqk[2*(size_t)D_*D_];
__device__ __align__(256) __nv_bfloat16 g_mh[(size_t)D_*D_];
__device__ __align__(256) __nv_bfloat16 g_e[(size_t)B_*P_*P_];
__device__ float g_wu[D_], g_wv[D_], g_c0[1];
__device__ float g_u[B_*P_], g_v[B_*P_];
__device__ float g_Z[B_*P_];
__device__ float g_xw[B_*D_];
__device__ float g_feats[4*B_*PR_];

// ---- helpers ----
__device__ __forceinline__ uint32_t smem_u32(const void* p){uint32_t a;asm("{.reg .u64 t; cvta.to.shared.u64 t,%1; cvt.u32.u64 %0,t;}":"=r"(a):"l"(p));return a;}
__device__ __forceinline__ void cpa16(uint32_t s,const void* g){asm volatile("cp.async.cg.shared.global [%0],[%1],16;"::"r"(s),"l"(g));}
__device__ __forceinline__ void cpa_commit(){asm volatile("cp.async.commit_group;");}
template<int N> __device__ __forceinline__ void cpa_wait(){asm volatile("cp.async.wait_group %0;"::"n"(N));}
__device__ __forceinline__ void ldsm4(uint32_t* r,uint32_t a){
    asm volatile("ldmatrix.sync.aligned.m8n8.x4.shared.b16 {%0,%1,%2,%3},[%4];":"=r"(r[0]),"=r"(r[1]),"=r"(r[2]),"=r"(r[3]):"r"(a));
}
__device__ __forceinline__ void ldsm4t(uint32_t* r,uint32_t a){
    asm volatile("ldmatrix.sync.aligned.m8n8.x4.trans.shared.b16 {%0,%1,%2,%3},[%4];":"=r"(r[0]),"=r"(r[1]),"=r"(r[2]),"=r"(r[3]):"r"(a));
}
__device__ __forceinline__ void mma16816(float* c,const uint32_t* a,const uint32_t* b){
    asm volatile("mma.sync.aligned.m16n8k16.row.col.f32.bf16.bf16.f32 {%0,%1,%2,%3},{%4,%5,%6,%7},{%8,%9},{%0,%1,%2,%3};"
      :"+f"(c[0]),"+f"(c[1]),"+f"(c[2]),"+f"(c[3])
      :"r"(a[0]),"r"(a[1]),"r"(a[2]),"r"(a[3]),"r"(b[0]),"r"(b[1]));
}
__device__ __forceinline__ uint32_t cvt2(float hi,float lo){uint32_t r;asm("cvt.rn.bf16x2.f32 %0,%1,%2;":"=r"(r):"f"(hi),"f"(lo));return r;}

// ---- mma.sync core (128x128, unchanged) ----
#define STG_BYTES 16384

template<bool BTRANS>
__device__ __forceinline__ void mm_core(
    const __nv_bfloat16* A, const __nv_bfloat16* Bm,
    float acc[4][4][4], char* smem)
{
    const int tid=threadIdx.x, wid=tid>>5, lane=tid&31;
    const int wm=wid>>2, wn=wid&3;
    const uint32_t sb=smem_u32(smem);

    auto fill=[&](int stg,int t){
        const char* Ab=(const char*)A;
        const char* Bb=(const char*)Bm;
        uint32_t as=sb+stg*STG_BYTES, bs=as+8192;
#pragma unroll
        for(int i=0;i<2;i++){
            int j=tid+256*i, r=j>>2, c=j&3;
            cpa16(as + r*64 + ((c^((r>>1)&3))<<4), Ab + (size_t)r*2048 + t*64 + c*16);
        }
        if(!BTRANS){
#pragma unroll
            for(int i=0;i<2;i++){
                int j=tid+256*i, r=j>>2, c=j&3;
                cpa16(bs + r*64 + ((c^((r>>1)&3))<<4), Bb + (size_t)r*2048 + t*64 + c*16);
            }
        } else {
#pragma unroll
            for(int i=0;i<2;i++){
                int j=tid+256*i, r=j>>4, c=j&15;
                cpa16(bs + r*256 + ((c^(r&7))<<4), Bb + (size_t)(t*32+r)*2048 + c*16);
            }
        }
        cpa_commit();
    };

    auto compute=[&](uint32_t as,uint32_t bs){
#pragma unroll
        for(int k0=0;k0<32;k0+=16){
            uint32_t a[4][4];
#pragma unroll
            for(int mf=0;mf<4;mf++){
                int r=wm*64+mf*16+(lane&15);
                int c=(k0>>3)+(lane>>4);
                ldsm4(a[mf], as + r*64 + ((c^((r>>1)&3))<<4));
            }
            uint32_t b[4][2];
            if(!BTRANS){
#pragma unroll
                for(int nf2=0;nf2<2;nf2++){
                    int r=wn*32+nf2*16+8*((lane>>3)&1)+(lane&7);
                    int c=(k0>>3)+(lane>>4);
                    uint32_t q[4]; ldsm4(q, bs + r*64 + ((c^((r>>1)&3))<<4));
                    b[nf2*2][0]=q[0]; b[nf2*2][1]=q[2]; b[nf2*2+1][0]=q[1]; b[nf2*2+1][1]=q[3];
                }
            } else {
#pragma unroll
                for(int nf2=0;nf2<2;nf2++){
                    int r=k0+8*((lane>>3)&1)+(lane&7);
                    int c=((wn*32+nf2*16)>>3)+(lane>>4);
                    uint32_t q[4]; ldsm4t(q, bs + r*256 + ((c^(r&7))<<4));
                    b[nf2*2][0]=q[0]; b[nf2*2][1]=q[1]; b[nf2*2+1][0]=q[2]; b[nf2*2+1][1]=q[3];
                }
            }
#pragma unroll
            for(int mf=0;mf<4;mf++)
#pragma unroll
                for(int nf=0;nf<4;nf++)
                    mma16816(acc[mf][nf], a[mf], b[nf]);
        }
    };

    const int T=32;
    fill(0,0); fill(1,1); fill(2,2);
    for(int tau4=0;tau4<T;tau4+=4){
#pragma unroll
        for(int u=0;u<4;u++){
            const int tau=tau4+u;
            cpa_wait<2>();
            __syncthreads();
            if(tau+3<T) fill((tau+3)&3, tau+3);
            compute(sb+u*STG_BYTES, sb+u*STG_BYTES+8192);
        }
    }
}

// ---- wide core for mm_sc: CTA 128x256, 512 threads, warp tile 32x64 ----
#define STG2_BYTES 24576   /* A 8KB + B 16KB */

__device__ __forceinline__ void mm_core_wide(
    const __nv_bfloat16* A, const __nv_bfloat16* Bm,
    float acc[2][8][4], char* smem)
{
    const int tid=threadIdx.x, wid=tid>>5, lane=tid&31;
    const int wm=wid>>2, wn=wid&3;   // 4m x 4n warps
    const uint32_t sb=smem_u32(smem);

    auto fill=[&](int stg,int t){
        const char* Ab=(const char*)A;
        const char* Bb=(const char*)Bm;
        uint32_t as=sb+stg*STG2_BYTES, bs=as+8192;
        {   // A: 512 chunks, 1 per thread
            int r=tid>>2, c=tid&3;
            cpa16(as + r*64 + ((c^((r>>1)&3))<<4), Ab + (size_t)r*2048 + t*64 + c*16);
        }
#pragma unroll
        for(int i=0;i<2;i++){   // B: 1024 chunks, 2 per thread
            int j=tid+512*i, r=j>>2, c=j&3;
            cpa16(bs + r*64 + ((c^((r>>1)&3))<<4), Bb + (size_t)r*2048 + t*64 + c*16);
        }
        cpa_commit();
    };

    auto compute=[&](uint32_t as,uint32_t bs){
#pragma unroll
        for(int k0=0;k0<32;k0+=16){
            uint32_t a[2][4];
#pragma unroll
            for(int mf=0;mf<2;mf++){
                int r=wm*32+mf*16+(lane&15);
                int c=(k0>>3)+(lane>>4);
                ldsm4(a[mf], as + r*64 + ((c^((r>>1)&3))<<4));
            }
            uint32_t b[8][2];
#pragma unroll
            for(int nf2=0;nf2<4;nf2++){
                int r=wn*64+nf2*16+8*((lane>>3)&1)+(lane&7);
                int c=(k0>>3)+(lane>>4);
                uint32_t q[4]; ldsm4(q, bs + r*64 + ((c^((r>>1)&3))<<4));
                b[nf2*2][0]=q[0]; b[nf2*2][1]=q[2]; b[nf2*2+1][0]=q[1]; b[nf2*2+1][1]=q[3];
            }
#pragma unroll
            for(int mf=0;mf<2;mf++)
#pragma unroll
                for(int nf=0;nf<8;nf++)
                    mma16816(acc[mf][nf], a[mf], b[nf]);
        }
    };

    const int T=32;
    fill(0,0); fill(1,1); fill(2,2);
    for(int tau4=0;tau4<T;tau4+=4){
#pragma unroll
        for(int u=0;u<4;u++){
            const int tau=tau4+u;
            cpa_wait<2>();
            __syncthreads();
            if(tau+3<T) fill((tau+3)&3, tau+3);
            compute(sb+u*STG2_BYTES, sb+u*STG2_BYTES+8192);
        }
    }
}

// ---- launch 1: prep_w ----
__global__ void prep_w_kernel(const float* __restrict__ Wq, const float* __restrict__ Wk,
                              __nv_bfloat16* __restrict__ wqk)
{
    size_t i=(size_t)blockIdx.x*1024+threadIdx.x;
    const size_t M=(size_t)D_*D_;
    wqk[i]=__float2bfloat16(i<M ? Wq[i] : Wk[i-M]);
}

// ---- launch 3: prep_x ----
__global__ void prep_x_kernel(const float4* __restrict__ X, uint2* __restrict__ xh)
{
    size_t i=(size_t)blockIdx.x*1024+threadIdx.x;
    float4 x=X[i];
    uint2 o; o.x=cvt2(x.y,x.x); o.y=cvt2(x.w,x.z);
    xh[i]=o;
}

// ---- launch 2: M = Wq@Wk^T + wu/wv/c0 ----
__global__ void __launch_bounds__(256,2) mm_m_wuv(
    const __nv_bfloat16* __restrict__ wqk, __nv_bfloat16* __restrict__ mh,
    const float* __restrict__ Wq,const float* __restrict__ Wk,
    const float* __restrict__ bq,const float* __restrict__ bk,
    float* __restrict__ wu,float* __restrict__ wv,float* __restrict__ c0)
{
    extern __shared__ __align__(1024) char smem[];
    int wid=threadIdx.x>>5, lane=threadIdx.x&31;
    if(blockIdx.y<8){
        const __nv_bfloat16* A = wqk + (size_t)blockIdx.y*128*D_;
        const __nv_bfloat16* Bm = wqk + (size_t)D_*D_ + (size_t)blockIdx.x*128*D_;
        float acc[4][4][4]={};
        mm_core<false>(A,Bm,acc,smem);
        int wm=wid>>2, wn=wid&3;
        size_t m0=(size_t)blockIdx.y*128 + wm*64 + lane/4;
        int n0=blockIdx.x*128 + wn*32 + (lane%4)*2;
#pragma unroll
        for(int mf=0;mf<4;mf++)
#pragma unroll
        for(int nf=0;nf<4;nf++){
            int n=n0+nf*8; size_t m=m0+mf*16;
            *(uint32_t*)(mh+m*D_+n)     = cvt2(acc[mf][nf][1], acc[mf][nf][0]);
            *(uint32_t*)(mh+(m+8)*D_+n) = cvt2(acc[mf][nf][3], acc[mf][nf][2]);
        }
    } else {
        for(int gw=blockIdx.x*8+wid; gw<2049; gw+=64){
            float a=0.f;
            if(gw<1024){
                const float* row=Wq+(size_t)gw*D_;
                for(int t=lane;t<D_;t+=32) a+=row[t]*bk[t];
#pragma unroll
                for(int o=16;o>0;o>>=1) a+=__shfl_xor_sync(~0u,a,o);
                if(lane==0) wu[gw]=a;
            } else if(gw<2048){
                int d=gw-1024;
                const float* row=Wk+(size_t)d*D_;
                for(int t=lane;t<D_;t+=32) a+=row[t]*bq[t];
#pragma unroll
                for(int o=16;o>0;o>>=1) a+=__shfl_xor_sync(~0u,a,o);
                if(lane==0) wv[d]=a;
            } else {
                for(int t=lane;t<D_;t+=32) a+=bq[t]*bk[t];
#pragma unroll
                for(int o=16;o>0;o>>=1) a+=__shfl_xor_sync(~0u,a,o);
                if(lane==0) c0[0]=a;
            }
        }
    }
}

// ---- launch 4: G = X@M + service CTAs ----
__global__ void __launch_bounds__(256,2) mm_g_uv(
    const __nv_bfloat16* __restrict__ Xh, const __nv_bfloat16* __restrict__ mh,
    __nv_bfloat16* __restrict__ gh,
    const float* __restrict__ wu,const float* __restrict__ wv,const float* __restrict__ c0,
    float* __restrict__ u,float* __restrict__ v,
    float* __restrict__ Z,float* __restrict__ xw,float* __restrict__ aw)
{
    extern __shared__ __align__(1024) char smem[];
    int wid=threadIdx.x>>5, lane=threadIdx.x&31;
    if(blockIdx.y<512){
        const __nv_bfloat16* A = Xh + (size_t)blockIdx.y*128*D_;
        const __nv_bfloat16* Bm = mh + blockIdx.x*128;
        float acc[4][4][4]={};
        mm_core<true>(A,Bm,acc,smem);
        int wm=wid>>2, wn=wid&3;
        size_t m0=(size_t)blockIdx.y*128 + wm*64 + lane/4;
        int n0=blockIdx.x*128 + wn*32 + (lane%4)*2;
#pragma unroll
        for(int mf=0;mf<4;mf++)
#pragma unroll
        for(int nf=0;nf<4;nf++){
            int n=n0+nf*8; size_t m=m0+mf*16;
            *(uint32_t*)(gh+m*D_+n)     = cvt2(acc[mf][nf][1], acc[mf][nf][0]);
            *(uint32_t*)(gh+(m+8)*D_+n) = cvt2(acc[mf][nf][3], acc[mf][nf][2]);
        }
    } else {
        int sidx=((blockIdx.y-512)*8+blockIdx.x)*256+threadIdx.x;
        if(sidx<B_*P_){ Z[sidx]=0.f; aw[sidx]=0.f; }
        if(sidx<B_*D_) xw[sidx]=0.f;
        int sw=sidx>>5;
        float cc=c0[0];
#pragma unroll
        for(int k2=0;k2<16;k2++){
            size_t row=(size_t)sw+4096u*k2;
            const uint4* xr=(const uint4*)(Xh+row*D_) + lane;
            float au=0.f, av=0.f;
#pragma unroll
            for(int it=0;it<4;it++){
                uint4 pk = xr[it*32];
                int base=(lane+it*32)*8;
                float4 u0=*(const float4*)(wu+base), u1=*(const float4*)(wu+base+4);
                float4 v0=*(const float4*)(wv+base), v1=*(const float4*)(wv+base+4);
                const __nv_bfloat162* pp=(const __nv_bfloat162*)&pk;
                float x0=__bfloat162float(pp[0].x), x1=__bfloat162float(pp[0].y);
                float x2=__bfloat162float(pp[1].x), x3=__bfloat162float(pp[1].y);
                float x4=__bfloat162float(pp[2].x), x5=__bfloat162float(pp[2].y);
                float x6=__bfloat162float(pp[3].x), x7=__bfloat162float(pp[3].y);
                au += x0*u0.x + x1*u0.y + x2*u0.z + x3*u0.w
                    + x4*u1.x + x5*u1.y + x6*u1.z + x7*u1.w;
                av += x0*v0.x + x1*v0.y + x2*v0.z + x3*v0.w
                    + x4*v1.x + x5*v1.y + x6*v1.z + x7*v1.w;
            }
#pragma unroll
            for(int o=16;o>0;o>>=1){ au+=__shfl_xor_sync(~0u,au,o); av+=__shfl_xor_sync(~0u,av,o); }
            if(lane==0){ u[row]=au+cc; v[row]=av; }
        }
    }
}

// ---- launch 5: scores (wide tile 128x256, 512 threads) ----
__global__ void __launch_bounds__(512,1) mm_sc(
    const __nv_bfloat16* __restrict__ gh, const __nv_bfloat16* __restrict__ xh,
    const float* __restrict__ u, const float* __restrict__ v,
    __nv_bfloat16* __restrict__ e, float* __restrict__ Z)
{
    extern __shared__ __align__(1024) char smem[];
    int z=blockIdx.z;
    const __nv_bfloat16* A = gh + (size_t)z*P_*D_ + (size_t)blockIdx.y*128*D_;
    const __nv_bfloat16* Bm = xh + (size_t)z*P_*D_ + (size_t)blockIdx.x*256*D_;
    float acc[2][8][4]={};
    mm_core_wide(A,Bm,acc,smem);

    __syncthreads();
    float* zs=(float*)smem;
    if(threadIdx.x<128) zs[threadIdx.x]=0.f;
    __syncthreads();

    const float sl2e = (1.f/32.f)*1.44269504f;
    int wid=threadIdx.x>>5, lane=threadIdx.x&31, wm=wid>>2, wn=wid&3;
    size_t m0=(size_t)blockIdx.y*128 + wm*32 + lane/4;
    int n0=blockIdx.x*256 + wn*64 + (lane%4)*2;
    __nv_bfloat16* C = e + (size_t)z*P_*P_;
    const float* ub = u + z*P_;
    const float* vb = v + z*P_;

    float rp[2][2]={};
#pragma unroll
    for(int mf=0;mf<2;mf++){
        size_t m=m0+mf*16;
        float um0=ub[m], um8=ub[m+8];
#pragma unroll
        for(int nf=0;nf<8;nf++){
            int n=n0+nf*8;
            float vn0=vb[n], vn1=vb[n+1];
            float e0=exp2f((acc[mf][nf][0]+um0+vn0)*sl2e);
            float e1=exp2f((acc[mf][nf][1]+um0+vn1)*sl2e);
            float e2=exp2f((acc[mf][nf][2]+um8+vn0)*sl2e);
            float e3=exp2f((acc[mf][nf][3]+um8+vn1)*sl2e);
            *(uint32_t*)(C+m*P_+n)     = cvt2(e1,e0);
            *(uint32_t*)(C+(m+8)*P_+n) = cvt2(e3,e2);
            rp[mf][0]+=e0+e1; rp[mf][1]+=e2+e3;
        }
    }
#pragma unroll
    for(int mf=0;mf<2;mf++)
#pragma unroll
    for(int h=0;h<2;h++){
        float vv=rp[mf][h];
        vv+=__shfl_xor_sync(~0u,vv,1);
        vv+=__shfl_xor_sync(~0u,vv,2);
        if((lane&3)==0) atomicAdd(&zs[wm*32+mf*16+h*8+(lane>>2)], vv);
    }
    __syncthreads();
    if(threadIdx.x<128)
        atomicAdd(&Z[z*P_+blockIdx.y*128+threadIdx.x], zs[threadIdx.x]);
}

// ---- launch 6: colsum ----
__global__ __launch_bounds__(256) void colsum_kernel(
    const __nv_bfloat16* __restrict__ e, const float* __restrict__ Z, float* __restrict__ aw)
{
    __shared__ float rv[256];
    int b=blockIdx.y, tid=threadIdx.x;
    int r0=blockIdx.z*256;
    rv[tid]=__fdividef(1.f,Z[b*P_+r0+tid]);
    __syncthreads();
    int j=blockIdx.x*1024+tid*4;
    const __nv_bfloat16* base=e+(size_t)b*P_*P_+(size_t)r0*P_+j;
    float a0=0.f,a1=0.f,a2=0.f,a3=0.f;
#pragma unroll 8
    for(int r=0;r<256;r++){
        uint2 pk=*(const uint2*)(base+(size_t)r*P_);
        const __nv_bfloat162* pp=(const __nv_bfloat162*)&pk;
        float w=rv[r];
        a0+=__bfloat162float(pp[0].x)*w;
        a1+=__bfloat162float(pp[0].y)*w;
        a2+=__bfloat162float(pp[1].x)*w;
        a3+=__bfloat162float(pp[1].y)*w;
    }
    const float s=1.f/(float)P_;
    atomicAdd(&aw[b*P_+j  ],a0*s);
    atomicAdd(&aw[b*P_+j+1],a1*s);
    atomicAdd(&aw[b*P_+j+2],a2*s);
    atomicAdd(&aw[b*P_+j+3],a3*s);
}

// ---- launch 7: xw = aw @ X ----
__global__ __launch_bounds__(1024) void awx_kernel(
    const float* __restrict__ aw,const __nv_bfloat16* __restrict__ Xh,float* __restrict__ xw)
{
    int b=blockIdx.y, qc=blockIdx.x*256;
    __shared__ float s_aw[256];
    if(threadIdx.x<256) s_aw[threadIdx.x]=aw[b*P_+qc+threadIdx.x];
    __syncthreads();
    float acc=0.f;
    const __nv_bfloat16* xb=Xh+((size_t)b*P_+qc)*D_+threadIdx.x;
#pragma unroll 4
    for(int q=0;q<256;q++) acc+=s_aw[q]*__bfloat162float(xb[(size_t)q*D_]);
    atomicAdd(&xw[b*D_+threadIdx.x],acc);
}

__device__ __forceinline__ float block_sum(float v,float* red)
{
#pragma unroll
    for(int o=16;o>0;o>>=1) v+=__shfl_xor_sync(~0u,v,o);
    int w=threadIdx.x>>5,l=threadIdx.x&31;
    if(l==0) red[w]=v;
    __syncthreads();
    if(w==0){
        float r=(threadIdx.x<(blockDim.x>>5))?red[threadIdx.x]:0.f;
#pragma unroll
        for(int o=16;o>0;o>>=1) r+=__shfl_xor_sync(~0u,r,o);
        if(l==0) red[0]=r;
    }
    __syncthreads();
    float out=red[0];
    __syncthreads();
    return out;
}

// ---- launch 8: MLPs (job0 fuses projv) ----
__global__ __launch_bounds__(1024) void mlp_kernel(
    const float* __restrict__ xw,const float* __restrict__ Wv,const float* __restrict__ bv,
    const float* __restrict__ thum,const float* __restrict__ text,
    const float* peW1,const float* peb1,const float* peg,const float* pebt,const float* peW2,const float* peb2,
    const float* teW1,const float* teb1,const float* teg,const float* tebt,const float* teW2,const float* teb2,
    const float* thW1,const float* thb1,const float* thg,const float* thbt,const float* thW2,const float* thb2,
    float* __restrict__ feats)
{
    int row=blockIdx.x, job=blockIdx.y;
    const float *x=nullptr,*W1,*b1,*g,*bt,*W2,*b2; int din;
    if(job==0){din=D_;W1=peW1;b1=peb1;g=peg;bt=pebt;W2=peW2;b2=peb2;}
    else if(job==1){x=thum+row*D_;din=D_;W1=thW1;b1=thb1;g=thg;bt=thbt;W2=thW2;b2=thb2;}
    else if(job==2){x=text+row*3*TD_+TD_;din=TD_;W1=teW1;b1=teb1;g=teg;bt=tebt;W2=teW2;b2=teb2;}
    else{x=text+row*3*TD_+2*TD_;din=TD_;W1=teW1;b1=teb1;g=teg;bt=tebt;W2=teW2;b2=teb2;}
    __shared__ float xs[1024], hs[1024], red[32];
    int tid=threadIdx.x;
    if(job==0){
        hs[tid]=xw[row*D_+tid];
        __syncthreads();
        float a=bv[tid];
#pragma unroll 8
        for(int k=0;k<D_;k++) a+=hs[k]*Wv[(size_t)k*D_+tid];
        xs[tid]=a;
        __syncthreads();
    } else {
        if(tid<din) xs[tid]=x[tid];
        __syncthreads();
    }
    float acc=b1[tid];
#pragma unroll 8
    for(int i=0;i<din;i++) acc+=xs[i]*W1[(size_t)i*1024+tid];
    float h=fmaxf(acc,0.f);
    float s1=block_sum(h,red), s2=block_sum(h*h,red);
    float mu=s1*(1.f/1024.f), var=s2*(1.f/1024.f)-mu*mu, rstd=rsqrtf(var+EPS_);
    hs[tid]=(h-mu)*rstd*g[tid]+bt[tid];
    __syncthreads();
    float o=0.f;
    if(tid<PR_){
        float a2=b2[tid];
#pragma unroll 8
        for(int i=0;i<1024;i++) a2+=hs[i]*W2[(size_t)i*PR_+tid];
        o=fmaxf(a2,0.f);
    }
    float nrm=block_sum(o*o,red);
    if(tid<PR_) feats[((size_t)job*B_+row)*PR_+tid]=o*rsqrtf(nrm);
}

// ---- launch 9: logits ----
__global__ __launch_bounds__(1024) void logits_kernel(
    const float* __restrict__ feats,const float* __restrict__ ls_p,float* __restrict__ out)
{
    int wid=threadIdx.x>>5, lane=threadIdx.x&31;
    float ls=expf(ls_p[0]);
    const float* pf=feats; const float* tf=feats+B_*PR_;
    const float* of=feats+2*B_*PR_; const float* hf=feats+3*B_*PR_;
    for(int p=wid;p<1024;p+=32){
        int i=p>>5, j=p&31;
        float lt=0.f,lp=0.f;
        for(int d=lane;d<PR_;d+=32){
            lt+=tf[i*PR_+d]*of[j*PR_+d];
            lp+=pf[i*PR_+d]*hf[j*PR_+d];
        }
#pragma unroll
        for(int o=16;o>0;o>>=1){ lt+=__shfl_xor_sync(~0u,lt,o); lp+=__shfl_xor_sync(~0u,lp,o); }
        if(lane==0){
            lt*=ls; lp*=ls;
            out[i*32+j]=lt; out[1024+i*32+j]=lp;
            out[2048+j*32+i]=lt; out[3072+j*32+i]=lp;
        }
    }
}

extern "C" void kernel_launch(void* const* d_in, const int* in_sizes, int n_in,
                              void* d_out, int out_size)
{
    const float* thum=(const float*)d_in[0];
    const float* patch=(const float*)d_in[1];
    const float* text=(const float*)d_in[2];
    const float* Wq=(const float*)d_in[3]; const float* bq=(const float*)d_in[4];
    const float* Wk=(const float*)d_in[5]; const float* bk=(const float*)d_in[6];
    const float* Wv=(const float*)d_in[7]; const float* bv=(const float*)d_in[8];
    const float* peW1=(const float*)d_in[9];  const float* peb1=(const float*)d_in[10];
    const float* peg =(const float*)d_in[11]; const float* pebt=(const float*)d_in[12];
    const float* peW2=(const float*)d_in[13]; const float* peb2=(const float*)d_in[14];
    const float* teW1=(const float*)d_in[15]; const float* teb1=(const float*)d_in[16];
    const float* teg =(const float*)d_in[17]; const float* tebt=(const float*)d_in[18];
    const float* teW2=(const float*)d_in[19]; const float* teb2=(const float*)d_in[20];
    const float* thW1=(const float*)d_in[21]; const float* thb1=(const float*)d_in[22];
    const float* thg =(const float*)d_in[23]; const float* thbt=(const float*)d_in[24];
    const float* thW2=(const float*)d_in[25]; const float* thb2=(const float*)d_in[26];
    const float* logit_scale=(const float*)d_in[27];

    float* out=(float*)d_out;
    float* aw_out=out+4096;

    __nv_bfloat16 *xh,*gh,*wqk,*mh,*e;
    float *wu,*wv,*c0,*u,*v,*Z,*xw,*ft;
    cudaGetSymbolAddress((void**)&xh,g_xh);
    cudaGetSymbolAddress((void**)&gh,g_gh);
    cudaGetSymbolAddress((void**)&wqk,g_wqk);
    cudaGetSymbolAddress((void**)&mh,g_mh);
    cudaGetSymbolAddress((void**)&e,g_e);
    cudaGetSymbolAddress((void**)&wu,g_wu);
    cudaGetSymbolAddress((void**)&wv,g_wv);
    cudaGetSymbolAddress((void**)&c0,g_c0);
    cudaGetSymbolAddress((void**)&u,g_u);
    cudaGetSymbolAddress((void**)&v,g_v);
    cudaGetSymbolAddress((void**)&Z,g_Z);
    cudaGetSymbolAddress((void**)&xw,g_xw);
    cudaGetSymbolAddress((void**)&ft,g_feats);

    const int SMEM =4*STG_BYTES;   // 64KB
    const int SMEM2=4*STG2_BYTES;  // 96KB
    cudaFuncSetAttribute(mm_m_wuv,cudaFuncAttributeMaxDynamicSharedMemorySize,SMEM);
    cudaFuncSetAttribute(mm_g_uv, cudaFuncAttributeMaxDynamicSharedMemorySize,SMEM);
    cudaFuncSetAttribute(mm_sc,   cudaFuncAttributeMaxDynamicSharedMemorySize,SMEM2);

    prep_w_kernel<<<2048,1024>>>(Wq,Wk,wqk);
    mm_m_wuv<<<dim3(8,9),256,SMEM>>>(wqk,mh,Wq,Wk,bq,bk,wu,wv,c0);
    prep_x_kernel<<<16384,1024>>>((const float4*)patch,(uint2*)xh);
    mm_g_uv<<<dim3(8,576),256,SMEM>>>(xh,mh,gh,wu,wv,c0,u,v,Z,xw,aw_out);
    // scores: CTA 128x256, 512 threads
    mm_sc<<<dim3(P_/256,P_/128,B_),512,SMEM2>>>(gh,xh,u,v,e,Z);
    colsum_kernel<<<dim3(P_/1024,B_,8),256>>>(e,Z,aw_out);
    awx_kernel<<<dim3(P_/256,B_),1024>>>(aw_out,xh,xw);
    mlp_kernel<<<dim3(B_,4),1024>>>(xw,Wv,bv,thum,text,
        peW1,peb1,peg,pebt,peW2,peb2,
        teW1,teb1,teg,tebt,teW2,teb2,
        thW1,thb1,thg,thbt,thW2,thb2,ft);
    logits_kernel<<<1,1024>>>(ft,logit_scale,out);
}

// round 17
// speedup vs baseline: 1.0185x; 1.0185x over previous
#include <cuda_runtime.h>
#include <cuda_bf16.h>
#include <math.h>
#include <cstdint>

#define B_ 32
#define P_ 2048
#define D_ 1024
#define TD_ 768
#define PR_ 512
#define EPS_ 1e-5f

__device__ __align__(256) __nv_bfloat16 g_xh[(size_t)B_*P_*D_];
__device__ __align__(256) __nv_bfloat16 g_gh[(size_t)B_*P_*D_];
__device__ __align__(256) __nv_bfloat16 g_wqk[2*(size_t)D_*D_];
__device__ __align__(256) __nv_bfloat16 g_mh[(size_t)D_*D_];
__device__ __align__(256) __nv_bfloat16 g_e[(size_t)B_*P_*P_];
__device__ float g_wu[D_], g_wv[D_], g_c0[1];
__device__ float g_u[B_*P_], g_v[B_*P_];
__device__ float g_Z[B_*P_];
__device__ float g_xw[B_*D_];
__device__ float g_feats[4*B_*PR_];

// ---- helpers ----
__device__ __forceinline__ uint32_t smem_u32(const void* p){uint32_t a;asm("{.reg .u64 t; cvta.to.shared.u64 t,%1; cvt.u32.u64 %0,t;}":"=r"(a):"l"(p));return a;}
__device__ __forceinline__ void cpa16(uint32_t s,const void* g){asm volatile("cp.async.cg.shared.global [%0],[%1],16;"::"r"(s),"l"(g));}
__device__ __forceinline__ void cpa_commit(){asm volatile("cp.async.commit_group;");}
template<int N> __device__ __forceinline__ void cpa_wait(){asm volatile("cp.async.wait_group %0;"::"n"(N));}
__device__ __forceinline__ void ldsm4(uint32_t* r,uint32_t a){
    asm volatile("ldmatrix.sync.aligned.m8n8.x4.shared.b16 {%0,%1,%2,%3},[%4];":"=r"(r[0]),"=r"(r[1]),"=r"(r[2]),"=r"(r[3]):"r"(a));
}
__device__ __forceinline__ void ldsm4t(uint32_t* r,uint32_t a){
    asm volatile("ldmatrix.sync.aligned.m8n8.x4.trans.shared.b16 {%0,%1,%2,%3},[%4];":"=r"(r[0]),"=r"(r[1]),"=r"(r[2]),"=r"(r[3]):"r"(a));
}
__device__ __forceinline__ void mma16816(float* c,const uint32_t* a,const uint32_t* b){
    asm volatile("mma.sync.aligned.m16n8k16.row.col.f32.bf16.bf16.f32 {%0,%1,%2,%3},{%4,%5,%6,%7},{%8,%9},{%0,%1,%2,%3};"
      :"+f"(c[0]),"+f"(c[1]),"+f"(c[2]),"+f"(c[3])
      :"r"(a[0]),"r"(a[1]),"r"(a[2]),"r"(a[3]),"r"(b[0]),"r"(b[1]));
}
__device__ __forceinline__ uint32_t cvt2(float hi,float lo){uint32_t r;asm("cvt.rn.bf16x2.f32 %0,%1,%2;":"=r"(r):"f"(hi),"f"(lo));return r;}

// ---- mma.sync core: acc[128x128 CTA tile] = A[128,1024] @ B^T ----
// LDSM smem offsets precomputed (loop-invariant) -> 1 IADD per LDSM in mainloop
#define STG_BYTES 16384

template<bool BTRANS>
__device__ __forceinline__ void mm_core(
    const __nv_bfloat16* A, const __nv_bfloat16* Bm,
    float acc[4][4][4], char* smem)
{
    const int tid=threadIdx.x, wid=tid>>5, lane=tid&31;
    const int wm=wid>>2, wn=wid&3;
    const uint32_t sb=smem_u32(smem);

    // precompute loop-invariant LDSM offsets (8 A + 4 B)
    uint32_t offA[2][4], offB[2][2];
#pragma unroll
    for(int k0i=0;k0i<2;k0i++){
#pragma unroll
        for(int mf=0;mf<4;mf++){
            int r=wm*64+mf*16+(lane&15), c=k0i*2+(lane>>4);
            offA[k0i][mf]=r*64+((c^((r>>1)&3))<<4);
        }
#pragma unroll
        for(int nf2=0;nf2<2;nf2++){
            if(!BTRANS){
                int r=wn*32+nf2*16+8*((lane>>3)&1)+(lane&7), c=k0i*2+(lane>>4);
                offB[k0i][nf2]=r*64+((c^((r>>1)&3))<<4);
            } else {
                int r=k0i*16+8*((lane>>3)&1)+(lane&7), c=((wn*32+nf2*16)>>3)+(lane>>4);
                offB[k0i][nf2]=r*256+((c^(r&7))<<4);
            }
        }
    }

    auto fill=[&](int stg,int t){
        const char* Ab=(const char*)A;
        const char* Bb=(const char*)Bm;
        uint32_t as=sb+stg*STG_BYTES, bs=as+8192;
#pragma unroll
        for(int i=0;i<2;i++){
            int j=tid+256*i, r=j>>2, c=j&3;
            cpa16(as + r*64 + ((c^((r>>1)&3))<<4), Ab + (size_t)r*2048 + t*64 + c*16);
        }
        if(!BTRANS){
#pragma unroll
            for(int i=0;i<2;i++){
                int j=tid+256*i, r=j>>2, c=j&3;
                cpa16(bs + r*64 + ((c^((r>>1)&3))<<4), Bb + (size_t)r*2048 + t*64 + c*16);
            }
        } else {
#pragma unroll
            for(int i=0;i<2;i++){
                int j=tid+256*i, r=j>>4, c=j&15;
                cpa16(bs + r*256 + ((c^(r&7))<<4), Bb + (size_t)(t*32+r)*2048 + c*16);
            }
        }
        cpa_commit();
    };

    auto compute=[&](uint32_t as,uint32_t bs){
#pragma unroll
        for(int k0i=0;k0i<2;k0i++){
            uint32_t a[4][4];
#pragma unroll
            for(int mf=0;mf<4;mf++)
                ldsm4(a[mf], as + offA[k0i][mf]);
            uint32_t b[4][2];
#pragma unroll
            for(int nf2=0;nf2<2;nf2++){
                uint32_t q[4];
                if(!BTRANS){
                    ldsm4(q, bs + offB[k0i][nf2]);
                    b[nf2*2][0]=q[0]; b[nf2*2][1]=q[2]; b[nf2*2+1][0]=q[1]; b[nf2*2+1][1]=q[3];
                } else {
                    ldsm4t(q, bs + offB[k0i][nf2]);
                    b[nf2*2][0]=q[0]; b[nf2*2][1]=q[1]; b[nf2*2+1][0]=q[2]; b[nf2*2+1][1]=q[3];
                }
            }
#pragma unroll
            for(int mf=0;mf<4;mf++)
#pragma unroll
                for(int nf=0;nf<4;nf++)
                    mma16816(acc[mf][nf], a[mf], b[nf]);
        }
    };

    const int T=32;
    fill(0,0); fill(1,1); fill(2,2);
    for(int tau4=0;tau4<T;tau4+=4){
#pragma unroll
        for(int u=0;u<4;u++){
            const int tau=tau4+u;
            cpa_wait<2>();
            __syncthreads();
            if(tau+3<T) fill((tau+3)&3, tau+3);
            compute(sb+u*STG_BYTES, sb+u*STG_BYTES+8192);
        }
    }
}

// ---- launch 1: prep_w ----
__global__ void prep_w_kernel(const float* __restrict__ Wq, const float* __restrict__ Wk,
                              __nv_bfloat16* __restrict__ wqk)
{
    size_t i=(size_t)blockIdx.x*1024+threadIdx.x;
    const size_t M=(size_t)D_*D_;
    wqk[i]=__float2bfloat16(i<M ? Wq[i] : Wk[i-M]);
}

// ---- launch 3: prep_x ----
__global__ void prep_x_kernel(const float4* __restrict__ X, uint2* __restrict__ xh)
{
    size_t i=(size_t)blockIdx.x*1024+threadIdx.x;
    float4 x=X[i];
    uint2 o; o.x=cvt2(x.y,x.x); o.y=cvt2(x.w,x.z);
    xh[i]=o;
}

// ---- launch 2: M = Wq@Wk^T + wu/wv/c0 ----
__global__ void __launch_bounds__(256,2) mm_m_wuv(
    const __nv_bfloat16* __restrict__ wqk, __nv_bfloat16* __restrict__ mh,
    const float* __restrict__ Wq,const float* __restrict__ Wk,
    const float* __restrict__ bq,const float* __restrict__ bk,
    float* __restrict__ wu,float* __restrict__ wv,float* __restrict__ c0)
{
    extern __shared__ __align__(1024) char smem[];
    int wid=threadIdx.x>>5, lane=threadIdx.x&31;
    if(blockIdx.y<8){
        const __nv_bfloat16* A = wqk + (size_t)blockIdx.y*128*D_;
        const __nv_bfloat16* Bm = wqk + (size_t)D_*D_ + (size_t)blockIdx.x*128*D_;
        float acc[4][4][4]={};
        mm_core<false>(A,Bm,acc,smem);
        int wm=wid>>2, wn=wid&3;
        size_t m0=(size_t)blockIdx.y*128 + wm*64 + lane/4;
        int n0=blockIdx.x*128 + wn*32 + (lane%4)*2;
#pragma unroll
        for(int mf=0;mf<4;mf++)
#pragma unroll
        for(int nf=0;nf<4;nf++){
            int n=n0+nf*8; size_t m=m0+mf*16;
            *(uint32_t*)(mh+m*D_+n)     = cvt2(acc[mf][nf][1], acc[mf][nf][0]);
            *(uint32_t*)(mh+(m+8)*D_+n) = cvt2(acc[mf][nf][3], acc[mf][nf][2]);
        }
    } else {
        for(int gw=blockIdx.x*8+wid; gw<2049; gw+=64){
            float a=0.f;
            if(gw<1024){
                const float* row=Wq+(size_t)gw*D_;
                for(int t=lane;t<D_;t+=32) a+=row[t]*bk[t];
#pragma unroll
                for(int o=16;o>0;o>>=1) a+=__shfl_xor_sync(~0u,a,o);
                if(lane==0) wu[gw]=a;
            } else if(gw<2048){
                int d=gw-1024;
                const float* row=Wk+(size_t)d*D_;
                for(int t=lane;t<D_;t+=32) a+=row[t]*bq[t];
#pragma unroll
                for(int o=16;o>0;o>>=1) a+=__shfl_xor_sync(~0u,a,o);
                if(lane==0) wv[d]=a;
            } else {
                for(int t=lane;t<D_;t+=32) a+=bq[t]*bk[t];
#pragma unroll
                for(int o=16;o>0;o>>=1) a+=__shfl_xor_sync(~0u,a,o);
                if(lane==0) c0[0]=a;
            }
        }
    }
}

// ---- launch 4: G = X@M + service CTAs ----
__global__ void __launch_bounds__(256,2) mm_g_uv(
    const __nv_bfloat16* __restrict__ Xh, const __nv_bfloat16* __restrict__ mh,
    __nv_bfloat16* __restrict__ gh,
    const float* __restrict__ wu,const float* __restrict__ wv,const float* __restrict__ c0,
    float* __restrict__ u,float* __restrict__ v,
    float* __restrict__ Z,float* __restrict__ xw,float* __restrict__ aw)
{
    extern __shared__ __align__(1024) char smem[];
    int wid=threadIdx.x>>5, lane=threadIdx.x&31;
    if(blockIdx.y<512){
        const __nv_bfloat16* A = Xh + (size_t)blockIdx.y*128*D_;
        const __nv_bfloat16* Bm = mh + blockIdx.x*128;
        float acc[4][4][4]={};
        mm_core<true>(A,Bm,acc,smem);
        int wm=wid>>2, wn=wid&3;
        size_t m0=(size_t)blockIdx.y*128 + wm*64 + lane/4;
        int n0=blockIdx.x*128 + wn*32 + (lane%4)*2;
#pragma unroll
        for(int mf=0;mf<4;mf++)
#pragma unroll
        for(int nf=0;nf<4;nf++){
            int n=n0+nf*8; size_t m=m0+mf*16;
            *(uint32_t*)(gh+m*D_+n)     = cvt2(acc[mf][nf][1], acc[mf][nf][0]);
            *(uint32_t*)(gh+(m+8)*D_+n) = cvt2(acc[mf][nf][3], acc[mf][nf][2]);
        }
    } else {
        int sidx=((blockIdx.y-512)*8+blockIdx.x)*256+threadIdx.x;
        if(sidx<B_*P_){ Z[sidx]=0.f; aw[sidx]=0.f; }
        if(sidx<B_*D_) xw[sidx]=0.f;
        int sw=sidx>>5;
        float cc=c0[0];
#pragma unroll
        for(int k2=0;k2<16;k2++){
            size_t row=(size_t)sw+4096u*k2;
            const uint4* xr=(const uint4*)(Xh+row*D_) + lane;
            float au=0.f, av=0.f;
#pragma unroll
            for(int it=0;it<4;it++){
                uint4 pk = xr[it*32];
                int base=(lane+it*32)*8;
                float4 u0=*(const float4*)(wu+base), u1=*(const float4*)(wu+base+4);
                float4 v0=*(const float4*)(wv+base), v1=*(const float4*)(wv+base+4);
                const __nv_bfloat162* pp=(const __nv_bfloat162*)&pk;
                float x0=__bfloat162float(pp[0].x), x1=__bfloat162float(pp[0].y);
                float x2=__bfloat162float(pp[1].x), x3=__bfloat162float(pp[1].y);
                float x4=__bfloat162float(pp[2].x), x5=__bfloat162float(pp[2].y);
                float x6=__bfloat162float(pp[3].x), x7=__bfloat162float(pp[3].y);
                au += x0*u0.x + x1*u0.y + x2*u0.z + x3*u0.w
                    + x4*u1.x + x5*u1.y + x6*u1.z + x7*u1.w;
                av += x0*v0.x + x1*v0.y + x2*v0.z + x3*v0.w
                    + x4*v1.x + x5*v1.y + x6*v1.z + x7*v1.w;
            }
#pragma unroll
            for(int o=16;o>0;o>>=1){ au+=__shfl_xor_sync(~0u,au,o); av+=__shfl_xor_sync(~0u,av,o); }
            if(lane==0){ u[row]=au+cc; v[row]=av; }
        }
    }
}

// ---- launch 5: scores e = exp((G@X^T + u + v)*scale) (bf16) + Z (smem staged) ----
__global__ void __launch_bounds__(256,2) mm_sc(
    const __nv_bfloat16* __restrict__ gh, const __nv_bfloat16* __restrict__ xh,
    const float* __restrict__ u, const float* __restrict__ v,
    __nv_bfloat16* __restrict__ e, float* __restrict__ Z)
{
    extern __shared__ __align__(1024) char smem[];
    int z=blockIdx.z;
    const __nv_bfloat16* A = gh + (size_t)z*P_*D_ + (size_t)blockIdx.y*128*D_;
    const __nv_bfloat16* Bm = xh + (size_t)z*P_*D_ + (size_t)blockIdx.x*128*D_;
    float acc[4][4][4]={};
    mm_core<false>(A,Bm,acc,smem);

    __syncthreads();
    float* zs=(float*)smem;
    if(threadIdx.x<128) zs[threadIdx.x]=0.f;
    __syncthreads();

    const float sl2e = (1.f/32.f)*1.44269504f;
    int wid=threadIdx.x>>5, lane=threadIdx.x&31, wm=wid>>2, wn=wid&3;
    size_t m0=(size_t)blockIdx.y*128 + wm*64 + lane/4;
    int n0=blockIdx.x*128 + wn*32 + (lane%4)*2;
    __nv_bfloat16* C = e + (size_t)z*P_*P_;
    const float* ub = u + z*P_;
    const float* vb = v + z*P_;

    float rp[4][2]={};
#pragma unroll
    for(int mf=0;mf<4;mf++){
        size_t m=m0+mf*16;
        float um0=ub[m], um8=ub[m+8];
#pragma unroll
        for(int nf=0;nf<4;nf++){
            int n=n0+nf*8;
            float vn0=vb[n], vn1=vb[n+1];
            float e0=exp2f((acc[mf][nf][0]+um0+vn0)*sl2e);
            float e1=exp2f((acc[mf][nf][1]+um0+vn1)*sl2e);
            float e2=exp2f((acc[mf][nf][2]+um8+vn0)*sl2e);
            float e3=exp2f((acc[mf][nf][3]+um8+vn1)*sl2e);
            *(uint32_t*)(C+m*P_+n)     = cvt2(e1,e0);
            *(uint32_t*)(C+(m+8)*P_+n) = cvt2(e3,e2);
            rp[mf][0]+=e0+e1; rp[mf][1]+=e2+e3;
        }
    }
#pragma unroll
    for(int mf=0;mf<4;mf++)
#pragma unroll
    for(int h=0;h<2;h++){
        float vv=rp[mf][h];
        vv+=__shfl_xor_sync(~0u,vv,1);
        vv+=__shfl_xor_sync(~0u,vv,2);
        if((lane&3)==0) atomicAdd(&zs[wm*64+mf*16+h*8+(lane>>2)], vv);
    }
    __syncthreads();
    if(threadIdx.x<128)
        atomicAdd(&Z[z*P_+blockIdx.y*128+threadIdx.x], zs[threadIdx.x]);
}

// ---- launch 6: colsum (8-way row split) ----
__global__ __launch_bounds__(256) void colsum_kernel(
    const __nv_bfloat16* __restrict__ e, const float* __restrict__ Z, float* __restrict__ aw)
{
    __shared__ float rv[256];
    int b=blockIdx.y, tid=threadIdx.x;
    int r0=blockIdx.z*256;
    rv[tid]=__fdividef(1.f,Z[b*P_+r0+tid]);
    __syncthreads();
    int j=blockIdx.x*1024+tid*4;
    const __nv_bfloat16* base=e+(size_t)b*P_*P_+(size_t)r0*P_+j;
    float a0=0.f,a1=0.f,a2=0.f,a3=0.f;
#pragma unroll 8
    for(int r=0;r<256;r++){
        uint2 pk=*(const uint2*)(base+(size_t)r*P_);
        const __nv_bfloat162* pp=(const __nv_bfloat162*)&pk;
        float w=rv[r];
        a0+=__bfloat162float(pp[0].x)*w;
        a1+=__bfloat162float(pp[0].y)*w;
        a2+=__bfloat162float(pp[1].x)*w;
        a3+=__bfloat162float(pp[1].y)*w;
    }
    const float s=1.f/(float)P_;
    atomicAdd(&aw[b*P_+j  ],a0*s);
    atomicAdd(&aw[b*P_+j+1],a1*s);
    atomicAdd(&aw[b*P_+j+2],a2*s);
    atomicAdd(&aw[b*P_+j+3],a3*s);
}

// ---- launch 7: xw = aw @ X ----
__global__ __launch_bounds__(1024) void awx_kernel(
    const float* __restrict__ aw,const __nv_bfloat16* __restrict__ Xh,float* __restrict__ xw)
{
    int b=blockIdx.y, qc=blockIdx.x*256;
    __shared__ float s_aw[256];
    if(threadIdx.x<256) s_aw[threadIdx.x]=aw[b*P_+qc+threadIdx.x];
    __syncthreads();
    float acc=0.f;
    const __nv_bfloat16* xb=Xh+((size_t)b*P_+qc)*D_+threadIdx.x;
#pragma unroll 4
    for(int q=0;q<256;q++) acc+=s_aw[q]*__bfloat162float(xb[(size_t)q*D_]);
    atomicAdd(&xw[b*D_+threadIdx.x],acc);
}

__device__ __forceinline__ float block_sum(float v,float* red)
{
#pragma unroll
    for(int o=16;o>0;o>>=1) v+=__shfl_xor_sync(~0u,v,o);
    int w=threadIdx.x>>5,l=threadIdx.x&31;
    if(l==0) red[w]=v;
    __syncthreads();
    if(w==0){
        float r=(threadIdx.x<(blockDim.x>>5))?red[threadIdx.x]:0.f;
#pragma unroll
        for(int o=16;o>0;o>>=1) r+=__shfl_xor_sync(~0u,r,o);
        if(l==0) red[0]=r;
    }
    __syncthreads();
    float out=red[0];
    __syncthreads();
    return out;
}

// ---- launch 8: MLPs (job0 fuses projv) ----
__global__ __launch_bounds__(1024) void mlp_kernel(
    const float* __restrict__ xw,const float* __restrict__ Wv,const float* __restrict__ bv,
    const float* __restrict__ thum,const float* __restrict__ text,
    const float* peW1,const float* peb1,const float* peg,const float* pebt,const float* peW2,const float* peb2,
    const float* teW1,const float* teb1,const float* teg,const float* tebt,const float* teW2,const float* teb2,
    const float* thW1,const float* thb1,const float* thg,const float* thbt,const float* thW2,const float* thb2,
    float* __restrict__ feats)
{
    int row=blockIdx.x, job=blockIdx.y;
    const float *x=nullptr,*W1,*b1,*g,*bt,*W2,*b2; int din;
    if(job==0){din=D_;W1=peW1;b1=peb1;g=peg;bt=pebt;W2=peW2;b2=peb2;}
    else if(job==1){x=thum+row*D_;din=D_;W1=thW1;b1=thb1;g=thg;bt=thbt;W2=thW2;b2=thb2;}
    else if(job==2){x=text+row*3*TD_+TD_;din=TD_;W1=teW1;b1=teb1;g=teg;bt=tebt;W2=teW2;b2=teb2;}
    else{x=text+row*3*TD_+2*TD_;din=TD_;W1=teW1;b1=teb1;g=teg;bt=tebt;W2=teW2;b2=teb2;}
    __shared__ float xs[1024], hs[1024], red[32];
    int tid=threadIdx.x;
    if(job==0){
        hs[tid]=xw[row*D_+tid];
        __syncthreads();
        float a=bv[tid];
#pragma unroll 8
        for(int k=0;k<D_;k++) a+=hs[k]*Wv[(size_t)k*D_+tid];
        xs[tid]=a;
        __syncthreads();
    } else {
        if(tid<din) xs[tid]=x[tid];
        __syncthreads();
    }
    float acc=b1[tid];
#pragma unroll 8
    for(int i=0;i<din;i++) acc+=xs[i]*W1[(size_t)i*1024+tid];
    float h=fmaxf(acc,0.f);
    float s1=block_sum(h,red), s2=block_sum(h*h,red);
    float mu=s1*(1.f/1024.f), var=s2*(1.f/1024.f)-mu*mu, rstd=rsqrtf(var+EPS_);
    hs[tid]=(h-mu)*rstd*g[tid]+bt[tid];
    __syncthreads();
    float o=0.f;
    if(tid<PR_){
        float a2=b2[tid];
#pragma unroll 8
        for(int i=0;i<1024;i++) a2+=hs[i]*W2[(size_t)i*PR_+tid];
        o=fmaxf(a2,0.f);
    }
    float nrm=block_sum(o*o,red);
    if(tid<PR_) feats[((size_t)job*B_+row)*PR_+tid]=o*rsqrtf(nrm);
}

// ---- launch 9: logits ----
__global__ __launch_bounds__(1024) void logits_kernel(
    const float* __restrict__ feats,const float* __restrict__ ls_p,float* __restrict__ out)
{
    int wid=threadIdx.x>>5, lane=threadIdx.x&31;
    float ls=expf(ls_p[0]);
    const float* pf=feats; const float* tf=feats+B_*PR_;
    const float* of=feats+2*B_*PR_; const float* hf=feats+3*B_*PR_;
    for(int p=wid;p<1024;p+=32){
        int i=p>>5, j=p&31;
        float lt=0.f,lp=0.f;
        for(int d=lane;d<PR_;d+=32){
            lt+=tf[i*PR_+d]*of[j*PR_+d];
            lp+=pf[i*PR_+d]*hf[j*PR_+d];
        }
#pragma unroll
        for(int o=16;o>0;o>>=1){ lt+=__shfl_xor_sync(~0u,lt,o); lp+=__shfl_xor_sync(~0u,lp,o); }
        if(lane==0){
            lt*=ls; lp*=ls;
            out[i*32+j]=lt; out[1024+i*32+j]=lp;
            out[2048+j*32+i]=lt; out[3072+j*32+i]=lp;
        }
    }
}

extern "C" void kernel_launch(void* const* d_in, const int* in_sizes, int n_in,
                              void* d_out, int out_size)
{
    const float* thum=(const float*)d_in[0];
    const float* patch=(const float*)d_in[1];
    const float* text=(const float*)d_in[2];
    const float* Wq=(const float*)d_in[3]; const float* bq=(const float*)d_in[4];
    const float* Wk=(const float*)d_in[5]; const float* bk=(const float*)d_in[6];
    const float* Wv=(const float*)d_in[7]; const float* bv=(const float*)d_in[8];
    const float* peW1=(const float*)d_in[9];  const float* peb1=(const float*)d_in[10];
    const float* peg =(const float*)d_in[11]; const float* pebt=(const float*)d_in[12];
    const float* peW2=(const float*)d_in[13]; const float* peb2=(const float*)d_in[14];
    const float* teW1=(const float*)d_in[15]; const float* teb1=(const float*)d_in[16];
    const float* teg =(const float*)d_in[17]; const float* tebt=(const float*)d_in[18];
    const float* teW2=(const float*)d_in[19]; const float* teb2=(const float*)d_in[20];
    const float* thW1=(const float*)d_in[21]; const float* thb1=(const float*)d_in[22];
    const float* thg =(const float*)d_in[23]; const float* thbt=(const float*)d_in[24];
    const float* thW2=(const float*)d_in[25]; const float* thb2=(const float*)d_in[26];
    const float* logit_scale=(const float*)d_in[27];

    float* out=(float*)d_out;
    float* aw_out=out+4096;

    __nv_bfloat16 *xh,*gh,*wqk,*mh,*e;
    float *wu,*wv,*c0,*u,*v,*Z,*xw,*ft;
    cudaGetSymbolAddress((void**)&xh,g_xh);
    cudaGetSymbolAddress((void**)&gh,g_gh);
    cudaGetSymbolAddress((void**)&wqk,g_wqk);
    cudaGetSymbolAddress((void**)&mh,g_mh);
    cudaGetSymbolAddress((void**)&e,g_e);
    cudaGetSymbolAddress((void**)&wu,g_wu);
    cudaGetSymbolAddress((void**)&wv,g_wv);
    cudaGetSymbolAddress((void**)&c0,g_c0);
    cudaGetSymbolAddress((void**)&u,g_u);
    cudaGetSymbolAddress((void**)&v,g_v);
    cudaGetSymbolAddress((void**)&Z,g_Z);
    cudaGetSymbolAddress((void**)&xw,g_xw);
    cudaGetSymbolAddress((void**)&ft,g_feats);

    const int SMEM=4*STG_BYTES; // 64KB
    cudaFuncSetAttribute(mm_m_wuv,cudaFuncAttributeMaxDynamicSharedMemorySize,SMEM);
    cudaFuncSetAttribute(mm_g_uv, cudaFuncAttributeMaxDynamicSharedMemorySize,SMEM);
    cudaFuncSetAttribute(mm_sc,   cudaFuncAttributeMaxDynamicSharedMemorySize,SMEM);

    prep_w_kernel<<<2048,1024>>>(Wq,Wk,wqk);
    mm_m_wuv<<<dim3(8,9),256,SMEM>>>(wqk,mh,Wq,Wk,bq,bk,wu,wv,c0);
    prep_x_kernel<<<16384,1024>>>((const float4*)patch,(uint2*)xh);
    mm_g_uv<<<dim3(8,576),256,SMEM>>>(xh,mh,gh,wu,wv,c0,u,v,Z,xw,aw_out);
    mm_sc<<<dim3(P_/128,P_/128,B_),256,SMEM>>>(gh,xh,u,v,e,Z);
    colsum_kernel<<<dim3(P_/1024,B_,8),256>>>(e,Z,aw_out);
    awx_kernel<<<dim3(P_/256,B_),1024>>>(aw_out,xh,xw);
    mlp_kernel<<<dim3(B_,4),1024>>>(xw,Wv,bv,thum,text,
        peW1,peb1,peg,pebt,peW2,peb2,
        teW1,teb1,teg,tebt,teW2,teb2,
        thW1,thb1,thg,thbt,thW2,thb2,ft);
    logits_kernel<<<1,1024>>>(ft,logit_scale,out);
}